// round 1
// baseline (speedup 1.0000x reference)
#include <cuda_runtime.h>
#include <math.h>

// Problem constants
#define T_TOK 2048
#define H_DIM 1024
#define E_EXP 32
#define I_DIM 2048
#define TOPK  2

// Tile config
#define BM 64
#define BN 64
#define BK 16

// -------- scratch (static device globals; no runtime allocation) --------
__device__ float g_mix[T_TOK * 96];                 // router qkv mix
__device__ float g_topw[T_TOK * 2];                 // per-token top2 softmax weights
__device__ int   g_counts[E_EXP];                   // tokens per expert
__device__ int   g_list[E_EXP * T_TOK];             // pair codes (t*2+slot) grouped by expert
__device__ float g_act[(size_t)T_TOK * 2 * I_DIM];  // SwiGLU activations per pair  (32 MB)
__device__ float g_outp[(size_t)T_TOK * 2 * H_DIM]; // per-pair FFN output          (16 MB)

// ------------------------------------------------------------------
__global__ void zero_counts_kernel() {
    if (threadIdx.x < E_EXP) g_counts[threadIdx.x] = 0;
}

// ------------------------------------------------------------------
// mix = x @ wqkv^T   [2048, 96], K=1024
__global__ __launch_bounds__(256) void mix_gemm_kernel(
    const float* __restrict__ x, const float* __restrict__ wqkv)
{
    __shared__ float As[BK][BM];
    __shared__ float Bs[BK][BN];
    const int M = T_TOK, N = 96, K = H_DIM;
    int m0 = blockIdx.y * BM, n0 = blockIdx.x * BN;
    int tid = threadIdx.x;
    int tx = tid & 15, ty = tid >> 4;
    int lm = tid >> 2, lk = (tid & 3) * 4;

    const float* Arow = x + (size_t)(m0 + lm) * K;            // m always < M here
    int brow = n0 + lm;
    const float* Brow = wqkv + (size_t)min(brow, N - 1) * K;
    bool bvalid = brow < N;

    float acc[4][4] = {};
    for (int k0 = 0; k0 < K; k0 += BK) {
        float4 av = *(const float4*)(Arow + k0 + lk);
        float4 bv = bvalid ? *(const float4*)(Brow + k0 + lk) : make_float4(0.f,0.f,0.f,0.f);
        As[lk+0][lm]=av.x; As[lk+1][lm]=av.y; As[lk+2][lm]=av.z; As[lk+3][lm]=av.w;
        Bs[lk+0][lm]=bv.x; Bs[lk+1][lm]=bv.y; Bs[lk+2][lm]=bv.z; Bs[lk+3][lm]=bv.w;
        __syncthreads();
        #pragma unroll
        for (int kk = 0; kk < BK; kk++) {
            float4 a = *(const float4*)&As[kk][ty*4];
            float4 b = *(const float4*)&Bs[kk][tx*4];
            float ar[4] = {a.x,a.y,a.z,a.w};
            float br[4] = {b.x,b.y,b.z,b.w};
            #pragma unroll
            for (int i = 0; i < 4; i++)
                #pragma unroll
                for (int j = 0; j < 4; j++)
                    acc[i][j] += ar[i] * br[j];
        }
        __syncthreads();
    }
    #pragma unroll
    for (int i = 0; i < 4; i++) {
        int m = m0 + ty*4 + i;
        #pragma unroll
        for (int j = 0; j < 4; j++) {
            int n = n0 + tx*4 + j;
            if (n < N) g_mix[(size_t)m * 96 + n] = acc[i][j];
        }
    }
}

// ------------------------------------------------------------------
// Router: per-token softmax-attention over experts, top-2, weights, lists.
__global__ void route_kernel()
{
    int t = blockIdx.x * 4 + (threadIdx.x >> 5);
    int lane = threadIdx.x & 31;
    if (t >= T_TOK) return;
    const float* mix = g_mix + (size_t)t * 96;
    float q  = mix[lane];
    float kf = mix[32 + lane];
    float vf = mix[64 + lane];

    // logits[lane] = sum_f softmax_f(q*k[f]) * v[f]
    float m = -INFINITY;
    #pragma unroll
    for (int f = 0; f < 32; f++) {
        float kk = __shfl_sync(0xffffffffu, kf, f);
        m = fmaxf(m, q * kk);
    }
    float s = 0.f, num = 0.f;
    #pragma unroll
    for (int f = 0; f < 32; f++) {
        float kk = __shfl_sync(0xffffffffu, kf, f);
        float vv = __shfl_sync(0xffffffffu, vf, f);
        float p = expf(q * kk - m);
        s += p; num += p * vv;
    }
    float logit = num / s;

    // top-1 (value desc, index asc on ties)
    float v1 = logit; int i1 = lane;
    #pragma unroll
    for (int off = 16; off > 0; off >>= 1) {
        float ov = __shfl_xor_sync(0xffffffffu, v1, off);
        int   oi = __shfl_xor_sync(0xffffffffu, i1, off);
        if (ov > v1 || (ov == v1 && oi < i1)) { v1 = ov; i1 = oi; }
    }
    // top-2
    float mval = (lane == i1) ? -INFINITY : logit;
    float v2 = mval; int i2 = lane;
    #pragma unroll
    for (int off = 16; off > 0; off >>= 1) {
        float ov = __shfl_xor_sync(0xffffffffu, v2, off);
        int   oi = __shfl_xor_sync(0xffffffffu, i2, off);
        if (ov > v2 || (ov == v2 && oi < i2)) { v2 = ov; i2 = oi; }
    }

    if (lane == 0) {
        float e2 = expf(v2 - v1);        // v2 <= v1
        float inv = 1.f / (1.f + e2);
        g_topw[t*2 + 0] = inv;
        g_topw[t*2 + 1] = e2 * inv;
        int p1 = atomicAdd(&g_counts[i1], 1);
        g_list[i1 * T_TOK + p1] = t*2 + 0;
        int p2 = atomicAdd(&g_counts[i2], 1);
        g_list[i2 * T_TOK + p2] = t*2 + 1;
    }
}

// ------------------------------------------------------------------
// GEMM1 + SwiGLU: act[code, i] = silu(x_t . wg_i) * (x_t . wu_i)
// ws layout per expert: [2I, H]; rows 0..I-1 = gate, I..2I-1 = up.
__global__ __launch_bounds__(256) void gemm1_silu_kernel(
    const float* __restrict__ x, const float* __restrict__ ws)
{
    int e = blockIdx.z;
    int ne = g_counts[e];
    int m0 = blockIdx.y * BM;
    if (m0 >= ne) return;
    int n0 = blockIdx.x * BN;

    __shared__ float As [BK][BM];
    __shared__ float Bgs[BK][BN];
    __shared__ float Bus[BK][BN];

    const float* Bg = ws + (size_t)e * (2 * I_DIM) * H_DIM;
    const float* Bu = Bg + (size_t)I_DIM * H_DIM;

    int tid = threadIdx.x;
    int tx = tid & 15, ty = tid >> 4;
    int lm = tid >> 2, lk = (tid & 3) * 4;

    int code = g_list[e * T_TOK + min(m0 + lm, ne - 1)];
    const float* Arow = x  + (size_t)(code >> 1) * H_DIM;
    const float* Bgr  = Bg + (size_t)(n0 + lm) * H_DIM;
    const float* Bur  = Bu + (size_t)(n0 + lm) * H_DIM;

    float accg[4][4] = {}, accu[4][4] = {};
    for (int k0 = 0; k0 < H_DIM; k0 += BK) {
        float4 av = *(const float4*)(Arow + k0 + lk);
        float4 bg = *(const float4*)(Bgr + k0 + lk);
        float4 bu = *(const float4*)(Bur + k0 + lk);
        As [lk+0][lm]=av.x; As [lk+1][lm]=av.y; As [lk+2][lm]=av.z; As [lk+3][lm]=av.w;
        Bgs[lk+0][lm]=bg.x; Bgs[lk+1][lm]=bg.y; Bgs[lk+2][lm]=bg.z; Bgs[lk+3][lm]=bg.w;
        Bus[lk+0][lm]=bu.x; Bus[lk+1][lm]=bu.y; Bus[lk+2][lm]=bu.z; Bus[lk+3][lm]=bu.w;
        __syncthreads();
        #pragma unroll
        for (int kk = 0; kk < BK; kk++) {
            float4 a  = *(const float4*)&As [kk][ty*4];
            float4 bg4= *(const float4*)&Bgs[kk][tx*4];
            float4 bu4= *(const float4*)&Bus[kk][tx*4];
            float ar[4]={a.x,a.y,a.z,a.w};
            float gg[4]={bg4.x,bg4.y,bg4.z,bg4.w};
            float uu[4]={bu4.x,bu4.y,bu4.z,bu4.w};
            #pragma unroll
            for (int i = 0; i < 4; i++)
                #pragma unroll
                for (int j = 0; j < 4; j++) {
                    accg[i][j] += ar[i] * gg[j];
                    accu[i][j] += ar[i] * uu[j];
                }
        }
        __syncthreads();
    }
    #pragma unroll
    for (int i = 0; i < 4; i++) {
        int m = m0 + ty*4 + i;
        if (m < ne) {
            int c = g_list[e * T_TOK + m];
            float* dst = g_act + (size_t)c * I_DIM + n0 + tx*4;
            #pragma unroll
            for (int j = 0; j < 4; j++) {
                float g = accg[i][j];
                float sg = g / (1.f + expf(-g));   // silu
                dst[j] = sg * accu[i][j];
            }
        }
    }
}

// ------------------------------------------------------------------
// GEMM2: outp[code, h] = act[code, :] . w2[e][h, :]   (K = I = 2048)
__global__ __launch_bounds__(256) void gemm2_kernel(
    const float* __restrict__ w2s)
{
    int e = blockIdx.z;
    int ne = g_counts[e];
    int m0 = blockIdx.y * BM;
    if (m0 >= ne) return;
    int n0 = blockIdx.x * BN;

    __shared__ float As[BK][BM];
    __shared__ float Bs[BK][BN];

    const float* B = w2s + (size_t)e * H_DIM * I_DIM;

    int tid = threadIdx.x;
    int tx = tid & 15, ty = tid >> 4;
    int lm = tid >> 2, lk = (tid & 3) * 4;

    int code = g_list[e * T_TOK + min(m0 + lm, ne - 1)];
    const float* Arow = g_act + (size_t)code * I_DIM;
    const float* Brow = B + (size_t)(n0 + lm) * I_DIM;

    float acc[4][4] = {};
    for (int k0 = 0; k0 < I_DIM; k0 += BK) {
        float4 av = *(const float4*)(Arow + k0 + lk);
        float4 bv = *(const float4*)(Brow + k0 + lk);
        As[lk+0][lm]=av.x; As[lk+1][lm]=av.y; As[lk+2][lm]=av.z; As[lk+3][lm]=av.w;
        Bs[lk+0][lm]=bv.x; Bs[lk+1][lm]=bv.y; Bs[lk+2][lm]=bv.z; Bs[lk+3][lm]=bv.w;
        __syncthreads();
        #pragma unroll
        for (int kk = 0; kk < BK; kk++) {
            float4 a = *(const float4*)&As[kk][ty*4];
            float4 b = *(const float4*)&Bs[kk][tx*4];
            float ar[4]={a.x,a.y,a.z,a.w};
            float br[4]={b.x,b.y,b.z,b.w};
            #pragma unroll
            for (int i = 0; i < 4; i++)
                #pragma unroll
                for (int j = 0; j < 4; j++)
                    acc[i][j] += ar[i] * br[j];
        }
        __syncthreads();
    }
    #pragma unroll
    for (int i = 0; i < 4; i++) {
        int m = m0 + ty*4 + i;
        if (m < ne) {
            int c = g_list[e * T_TOK + m];
            float* dst = g_outp + (size_t)c * H_DIM + n0 + tx*4;
            #pragma unroll
            for (int j = 0; j < 4; j++) dst[j] = acc[i][j];
        }
    }
}

// ------------------------------------------------------------------
// y[t] = w0 * outp[2t] + w1 * outp[2t+1]
__global__ void combine_kernel(float* __restrict__ y)
{
    int t = blockIdx.x;
    float w0 = g_topw[t*2 + 0];
    float w1 = g_topw[t*2 + 1];
    const float4* a = (const float4*)(g_outp + (size_t)(t*2    ) * H_DIM);
    const float4* b = (const float4*)(g_outp + (size_t)(t*2 + 1) * H_DIM);
    float4* o = (float4*)(y + (size_t)t * H_DIM);
    int i = threadIdx.x;            // 256 threads, 256 float4 per row
    float4 av = a[i], bv = b[i];
    float4 r;
    r.x = w0*av.x + w1*bv.x;
    r.y = w0*av.y + w1*bv.y;
    r.z = w0*av.z + w1*bv.z;
    r.w = w0*av.w + w1*bv.w;
    o[i] = r;
}

// ------------------------------------------------------------------
extern "C" void kernel_launch(void* const* d_in, const int* in_sizes, int n_in,
                              void* d_out, int out_size)
{
    const float* x    = (const float*)d_in[0];   // [2048, 1024]
    const float* wqkv = (const float*)d_in[1];   // [96, 1024]
    const float* ws   = (const float*)d_in[2];   // [32, 4096, 1024]
    const float* w2s  = (const float*)d_in[3];   // [32, 1024, 2048]
    float* y = (float*)d_out;                    // [2048, 1024]

    zero_counts_kernel<<<1, 32>>>();

    dim3 gmix((96 + BN - 1) / BN, T_TOK / BM);           // (2, 32)
    mix_gemm_kernel<<<gmix, 256>>>(x, wqkv);

    route_kernel<<<T_TOK / 4, 128>>>();

    dim3 g1(I_DIM / BN, T_TOK / BM, E_EXP);              // (32, 32, 32)
    gemm1_silu_kernel<<<g1, 256>>>(x, ws);

    dim3 g2(H_DIM / BN, T_TOK / BM, E_EXP);              // (16, 32, 32)
    gemm2_kernel<<<g2, 256>>>(w2s);

    combine_kernel<<<T_TOK, 256>>>(y);
}